// round 17
// baseline (speedup 1.0000x reference)
#include <cuda_runtime.h>
#include <math.h>

// DiceLoss: logits [8,19,512,512] f32, targets [8,512,512] int32 (harness downcasts i64)
#define NC 19
#define HW4 65536LL   // (512*512)/4 float4-groups per image-channel

// Scratch: probs_sum[0..18], inter[19..37], cnt[38..56]
__device__ float g_acc[3 * NC];
__device__ unsigned int g_done;

__global__ __launch_bounds__(128, 8) void dice_fused_kernel(
    const float* __restrict__ logits,
    const int* __restrict__ targets,
    long long npix,
    float* __restrict__ out)
{
    __shared__ float s_inter[NC];
    __shared__ float s_cnt[NC];
    __shared__ float s_psum[NC];
    __shared__ int   s_last;

    const int tid  = threadIdx.x;
    const int lane = tid & 31;
    const int s    = lane & 3;        // channel-slot within quad
    const int cb   = s * 5;           // channel base: 0,5,10,15

    if (tid < NC) { s_inter[tid] = 0.0f; s_cnt[tid] = 0.0f; s_psum[tid] = 0.0f; }
    __syncthreads();

    float acc[5];
#pragma unroll
    for (int j = 0; j < 5; j++) acc[j] = 0.0f;

    const long long nquads = npix >> 2;                      // float4 pixel-groups
    const long long qstride = ((long long)gridDim.x * blockDim.x) >> 2;
    const float4* __restrict__ lg4 = (const float4*)logits;
    const int4*   __restrict__ tg4 = (const int4*)targets;

    long long myq = (((long long)blockIdx.x * blockDim.x + tid) >> 2);
    // warp-uniform trip count: loop on the warp's first quad index
    long long q0  = (((long long)blockIdx.x * blockDim.x + (tid & ~31)) >> 2);

    for (; q0 < nquads; q0 += qstride, myq += qstride) {
        const bool act = (myq < nquads);
        const long long qc = act ? myq : (nquads - 1);       // clamped, safe address

        const int4 t = __ldg(&tg4[qc]);                      // quad-broadcast line
        const long long b  = qc >> 16;                       // qc / HW4
        const long long hw = qc & (HW4 - 1);                 // qc % HW4
        const float4* __restrict__ base = lg4 + b * (long long)NC * HW4 + hw;

        // 5 channel-slot loads: 512B per LDG across the warp (4 slots x 128B runs).
        float4 e[5];
#pragma unroll
        for (int j = 0; j < 5; j++) {
            const int c  = cb + j;
            const int ca = (c < NC) ? c : (NC - 1);          // slot 19 clamped
            e[j] = __ldg(base + (long long)ca * HW4);
        }
#pragma unroll
        for (int j = 0; j < 5; j++) {
            const bool cv = (cb + j) < NC;                   // mask the clamped slot
            e[j].x = cv ? __expf(e[j].x) : 0.0f;
            e[j].y = cv ? __expf(e[j].y) : 0.0f;
            e[j].z = cv ? __expf(e[j].z) : 0.0f;
            e[j].w = cv ? __expf(e[j].w) : 0.0f;
        }

        // Partial softmax denominators; quad-reduce with 2 shfl rounds.
        float sx = e[0].x + e[1].x + e[2].x + e[3].x + e[4].x;
        float sy = e[0].y + e[1].y + e[2].y + e[3].y + e[4].y;
        float sz = e[0].z + e[1].z + e[2].z + e[3].z + e[4].z;
        float sw = e[0].w + e[1].w + e[2].w + e[3].w + e[4].w;
#pragma unroll
        for (int o = 1; o <= 2; o <<= 1) {
            sx += __shfl_xor_sync(0xffffffffu, sx, o);
            sy += __shfl_xor_sync(0xffffffffu, sy, o);
            sz += __shfl_xor_sync(0xffffffffu, sz, o);
            sw += __shfl_xor_sync(0xffffffffu, sw, o);
        }

        const bool v0 = act && ((unsigned)t.x < NC);
        const bool v1 = act && ((unsigned)t.y < NC);
        const bool v2 = act && ((unsigned)t.z < NC);
        const bool v3 = act && ((unsigned)t.w < NC);

        // Fold validity into normalization: masked probs everywhere.
        const float ix = v0 ? __frcp_rn(sx) : 0.0f;
        const float iy = v1 ? __frcp_rn(sy) : 0.0f;
        const float iz = v2 ? __frcp_rn(sz) : 0.0f;
        const float iw = v3 ? __frcp_rn(sw) : 0.0f;

        float g0 = 0.f, g1 = 0.f, g2 = 0.f, g3 = 0.f;
#pragma unroll
        for (int j = 0; j < 5; j++) {
            const float px = e[j].x * ix;
            const float py = e[j].y * iy;
            const float pz = e[j].z * iz;
            const float pw = e[j].w * iw;
            acc[j] += (px + py) + (pz + pw);
            const int c = cb + j;                            // c==19 never matches t
            if (c == t.x) g0 = px;
            if (c == t.y) g1 = py;
            if (c == t.z) g2 = pz;
            if (c == t.w) g3 = pw;
        }
        // Owner-lane atomics (t in [cb, cb+5) -> exactly one lane per pixel).
        if (v0 && t.x >= cb && t.x < cb + 5) { atomicAdd(&s_inter[t.x], g0); atomicAdd(&s_cnt[t.x], 1.f); }
        if (v1 && t.y >= cb && t.y < cb + 5) { atomicAdd(&s_inter[t.y], g1); atomicAdd(&s_cnt[t.y], 1.f); }
        if (v2 && t.z >= cb && t.z < cb + 5) { atomicAdd(&s_inter[t.z], g2); atomicAdd(&s_cnt[t.z], 1.f); }
        if (v3 && t.w >= cb && t.w < cb + 5) { atomicAdd(&s_inter[t.w], g3); atomicAdd(&s_cnt[t.w], 1.f); }
    }

    // Scalar tail (npix % 4; 0 for this shape) — one thread.
    if (blockIdx.x == 0 && tid == 0) {
        for (long long p = nquads << 2; p < npix; p++) {
            const int t = targets[p];
            if ((unsigned)t >= NC) continue;
            const long long b  = p >> 18;
            const long long hw = p & ((1LL << 18) - 1);
            const float* bp = logits + b * (long long)NC * (HW4 * 4) + hw;
            float ee[NC]; float ssum = 0.f;
#pragma unroll
            for (int c = 0; c < NC; c++) { ee[c] = __expf(bp[(long long)c * HW4 * 4]); ssum += ee[c]; }
            const float inv = __frcp_rn(ssum);
            // fold into this thread's acc slots (s==0, cb==0): only classes 0..4 fit;
            // add the rest directly to s_psum via atomics (tail is <=3 pixels, cost ~0).
#pragma unroll
            for (int c = 0; c < NC; c++) atomicAdd(&s_psum[c], ee[c] * inv);
            atomicAdd(&s_inter[t], ee[t] * inv);
            atomicAdd(&s_cnt[t], 1.f);
        }
    }

    // psum: reduce acc[j] (class cb+j) across the 8 quads of each warp.
#pragma unroll
    for (int j = 0; j < 5; j++) {
        float v = acc[j];
        v += __shfl_xor_sync(0xffffffffu, v, 4);
        v += __shfl_xor_sync(0xffffffffu, v, 8);
        v += __shfl_xor_sync(0xffffffffu, v, 16);
        if (lane < 4) {
            const int c = cb + j;
            if (c < NC) atomicAdd(&s_psum[c], v);
        }
    }
    __syncthreads();

    // One global atomic per class per block.
    if (tid < NC) {
        atomicAdd(&g_acc[tid],          s_psum[tid]);
        atomicAdd(&g_acc[NC + tid],     s_inter[tid]);
        atomicAdd(&g_acc[2 * NC + tid], s_cnt[tid]);
    }

    // Last-block-done: finalize + reset scratch for the next (graph-replayed) call.
    __threadfence();
    if (tid == 0) {
        unsigned prev = atomicAdd(&g_done, 1u);
        s_last = (prev == gridDim.x - 1) ? 1 : 0;
    }
    __syncthreads();

    if (s_last) {
        if (tid < 32) {
            float contrib = 0.0f;
            float cntv = 0.0f;
            if (tid < NC) {
                // atomic reads bypass potentially-stale L1
                const float psum  = atomicAdd(&g_acc[tid], 0.0f);
                const float inter = atomicAdd(&g_acc[NC + tid], 0.0f);
                const float cnt   = atomicAdd(&g_acc[2 * NC + tid], 0.0f);
                contrib = 1.0f - (2.0f * inter + 1.0f) / (psum + cnt + 1.0f);
                cntv = cnt;
            }
#pragma unroll
            for (int o = 16; o > 0; o >>= 1) {
                contrib += __shfl_xor_sync(0xffffffffu, contrib, o);
                cntv    += __shfl_xor_sync(0xffffffffu, cntv, o);
            }
            if (tid == 0)
                out[0] = (cntv > 0.0f) ? (contrib / (float)NC) : 0.0f;
        }
        __syncthreads();
        if (tid < 3 * NC) g_acc[tid] = 0.0f;
        if (tid == 0) g_done = 0u;
    }
}

extern "C" void kernel_launch(void* const* d_in, const int* in_sizes, int n_in,
                              void* d_out, int out_size) {
    const float* logits  = (const float*)d_in[0];
    const int*   targets = (const int*)d_in[1];
    float* out = (float*)d_out;

    const long long npix = (long long)in_sizes[1];   // B*H*W = 2,097,152

    dice_fused_kernel<<<1184, 128>>>(logits, targets, npix, out);
}